// round 1
// baseline (speedup 1.0000x reference)
#include <cuda_runtime.h>
#include <math.h>
#include <stdint.h>

// ---------------------------------------------------------------------------
// RetentiveNetwork forward, fp32 SIMT baseline.
// L=2, H=2048, HEADS=8, HEAD=256, FF=8192, B=4, S=1024.
// ---------------------------------------------------------------------------

constexpr int LAYERS = 2;
constexpr int Hdim   = 2048;
constexpr int NH     = 8;
constexpr int HD     = 256;     // head dim
constexpr int FFdim  = 8192;
constexpr int Bn     = 4;
constexpr int Sn     = 1024;
constexpr int MT     = Bn * Sn; // 4096 tokens

// ---------------- scratch (static device allocations; no cudaMalloc) -------
__device__ float g_xn [MT * Hdim];
__device__ float g_q  [MT * Hdim];
__device__ float g_k  [MT * Hdim];
__device__ float g_v  [MT * Hdim];
__device__ float g_gt [MT * Hdim];
__device__ float g_y  [MT * Hdim];
__device__ float g_z  [MT * Hdim];
__device__ float g_ret[MT * Hdim];
__device__ float g_x1 [MT * Hdim];
__device__ float g_sc [(size_t)Bn * NH * Sn * Sn];   // 33.5M floats
__device__ float g_ffn[(size_t)MT * FFdim];          // 33.5M floats

// ---------------- block reduction helper ------------------------------------
__device__ __forceinline__ float blockReduce(float v, float* sh) {
    int lane = threadIdx.x & 31, w = threadIdx.x >> 5;
    #pragma unroll
    for (int o = 16; o; o >>= 1) v += __shfl_xor_sync(0xffffffffu, v, o);
    if (lane == 0) sh[w] = v;
    __syncthreads();
    if (w == 0) {
        float r = (lane < (int)(blockDim.x >> 5)) ? sh[lane] : 0.f;
        #pragma unroll
        for (int o = 4; o; o >>= 1) r += __shfl_xor_sync(0xffffffffu, r, o);
        if (lane == 0) sh[0] = r;
    }
    __syncthreads();
    float res = sh[0];
    __syncthreads();
    return res;
}

// ---------------- LayerNorm: one block (256 thr) per token ------------------
__global__ void ln_k(const float* __restrict__ x, const float* __restrict__ g,
                     const float* __restrict__ b, float* __restrict__ o) {
    __shared__ float sh[8];
    int tok = blockIdx.x;
    const float* xp = x + (size_t)tok * Hdim;
    float* op = o + (size_t)tok * Hdim;
    int t = threadIdx.x;
    float v[8];
    float s = 0.f;
    #pragma unroll
    for (int i = 0; i < 8; i++) { v[i] = xp[t + 256 * i]; s += v[i]; }
    float mu = blockReduce(s, sh) * (1.f / Hdim);
    float ss = 0.f;
    #pragma unroll
    for (int i = 0; i < 8; i++) { float d = v[i] - mu; ss += d * d; }
    float var = blockReduce(ss, sh) * (1.f / Hdim);
    float rs = rsqrtf(var + 1e-5f);
    #pragma unroll
    for (int i = 0; i < 8; i++) {
        int c = t + 256 * i;
        op[c] = (v[i] - mu) * rs * g[c] + b[c];
    }
}

// ---------------- GroupNorm + SiLU gate: one block per (token, head) --------
__global__ void gn_gate_k(const float* __restrict__ y, const float* __restrict__ gate,
                          const float* __restrict__ gg, const float* __restrict__ gb,
                          float* __restrict__ z) {
    __shared__ float sh[8];
    int grp = blockIdx.x;                 // tok*NH + h
    int h = grp & (NH - 1);
    size_t base = (size_t)(grp >> 3) * Hdim + (size_t)h * HD;
    int t = threadIdx.x;                  // 256 threads == HD
    float val = y[base + t];
    float mu = blockReduce(val, sh) * (1.f / HD);
    float d = val - mu;
    float var = blockReduce(d * d, sh) * (1.f / HD);
    float rs = rsqrtf(var + 1e-5f);
    int c = h * HD + t;
    float gv = gate[base + t];
    float silu = gv / (1.f + expf(-gv));
    z[base + t] = (d * rs * gg[c] + gb[c]) * silu;
}

// ---------------- GEMM: 128x128x8 tiles, 256 threads, 8x8 per thread --------
constexpr int BM = 128, BN = 128, BK = 8, PAD = 4;

enum { EPI_NONE = 0, EPI_DECAY = 1, EPI_RES = 2, EPI_BIAS_GELU = 3, EPI_BIAS_RES = 4 };

// All dims used are exact multiples of the tile sizes: no bounds checks.
// TRANSB: B given as [N,K] row-major (used for q @ k^T).
// TRILA:  A is lower-triangular-by-row-block (scores): clamp K to row0+BM.
template<bool TRANSB, int EPI, bool TRILA>
__global__ void __launch_bounds__(256, 2)
gemm_k(const float* __restrict__ A, const float* __restrict__ Bm, float* __restrict__ C,
       int M, int N, int K, int lda, int ldb, int ldc,
       long long sAb, long long sAh, long long sBb, long long sBh,
       long long sCb, long long sCh, int ZD,
       const float* __restrict__ bias, const float* __restrict__ res)
{
    __shared__ __align__(16) float As[2][BK][BM + PAD];
    __shared__ __align__(16) float Bs[2][BK][BN + PAD];

    int t = threadIdx.x;
    int row0 = blockIdx.y * BM;
    int col0 = blockIdx.x * BN;
    int z = blockIdx.z;
    int hh = z % ZD;
    long long bb = z / ZD;
    A  += bb * sAb + (long long)hh * sAh;
    Bm += bb * sBb + (long long)hh * sBh;
    C  += bb * sCb + (long long)hh * sCh;

    int r = (t >> 4) * 8;   // thread's row offset in tile
    int c = (t & 15) * 8;   // thread's col offset in tile

    // Score blocks strictly above the causal diagonal are identically zero:
    // write zeros and skip all compute.
    if (EPI == EPI_DECAY && row0 + BM <= col0) {
        float4 zz = make_float4(0.f, 0.f, 0.f, 0.f);
        #pragma unroll
        for (int i = 0; i < 8; i++) {
            *(float4*)&C[(size_t)(row0 + r + i) * ldc + col0 + c]     = zz;
            *(float4*)&C[(size_t)(row0 + r + i) * ldc + col0 + c + 4] = zz;
        }
        return;
    }

    int Kend = TRILA ? min(K, row0 + BM) : K;
    int nk = Kend / BK;

    // global->shared load mapping
    int arow = t >> 1, acol = (t & 1) * 4;
    const float* Aptr = A + (size_t)(row0 + arow) * lda + acol;
    float4 aReg = *(const float4*)Aptr;

    int bn_ = 0, bk_ = 0, brow = 0, bcol = 0;
    const float* Bptr;
    if (TRANSB) {
        bn_ = t >> 1; bk_ = (t & 1) * 4;
        Bptr = Bm + (size_t)(col0 + bn_) * ldb + bk_;
    } else {
        brow = t >> 5; bcol = (t & 31) * 4;
        Bptr = Bm + (size_t)brow * ldb + col0 + bcol;
    }
    float4 bReg = *(const float4*)Bptr;

    // stage 0
    As[0][acol + 0][arow] = aReg.x; As[0][acol + 1][arow] = aReg.y;
    As[0][acol + 2][arow] = aReg.z; As[0][acol + 3][arow] = aReg.w;
    if (TRANSB) {
        Bs[0][bk_ + 0][bn_] = bReg.x; Bs[0][bk_ + 1][bn_] = bReg.y;
        Bs[0][bk_ + 2][bn_] = bReg.z; Bs[0][bk_ + 3][bn_] = bReg.w;
    } else {
        *(float4*)&Bs[0][brow][bcol] = bReg;
    }
    __syncthreads();

    float acc[8][8];
    #pragma unroll
    for (int i = 0; i < 8; i++)
        #pragma unroll
        for (int j = 0; j < 8; j++) acc[i][j] = 0.f;

    for (int kt = 0; kt < nk; kt++) {
        int cur = kt & 1;
        if (kt + 1 < nk) {
            aReg = *(const float4*)(Aptr + (kt + 1) * BK);
            if (TRANSB) bReg = *(const float4*)(Bptr + (kt + 1) * BK);
            else        bReg = *(const float4*)(Bptr + (size_t)(kt + 1) * BK * ldb);
        }
        #pragma unroll
        for (int kk = 0; kk < BK; kk++) {
            float4 a0 = *(float4*)&As[cur][kk][r];
            float4 a1 = *(float4*)&As[cur][kk][r + 4];
            float4 b0 = *(float4*)&Bs[cur][kk][c];
            float4 b1 = *(float4*)&Bs[cur][kk][c + 4];
            float av[8] = {a0.x, a0.y, a0.z, a0.w, a1.x, a1.y, a1.z, a1.w};
            float bv[8] = {b0.x, b0.y, b0.z, b0.w, b1.x, b1.y, b1.z, b1.w};
            #pragma unroll
            for (int i = 0; i < 8; i++)
                #pragma unroll
                for (int j = 0; j < 8; j++)
                    acc[i][j] = fmaf(av[i], bv[j], acc[i][j]);
        }
        if (kt + 1 < nk) {
            int nxt = cur ^ 1;
            As[nxt][acol + 0][arow] = aReg.x; As[nxt][acol + 1][arow] = aReg.y;
            As[nxt][acol + 2][arow] = aReg.z; As[nxt][acol + 3][arow] = aReg.w;
            if (TRANSB) {
                Bs[nxt][bk_ + 0][bn_] = bReg.x; Bs[nxt][bk_ + 1][bn_] = bReg.y;
                Bs[nxt][bk_ + 2][bn_] = bReg.z; Bs[nxt][bk_ + 3][bn_] = bReg.w;
            } else {
                *(float4*)&Bs[nxt][brow][bcol] = bReg;
            }
        }
        __syncthreads();
    }

    // epilogue
    float lg = 0.f;
    if (EPI == EPI_DECAY) {
        // gamma_h = 1 - exp(linspace(ln(1/32), ln(1/512), 8))[h]
        float gamma = 1.f - expf(-(3.46573590f + 0.396084103f * (float)hh));
        lg = logf(gamma);
    }
    #pragma unroll
    for (int i = 0; i < 8; i++) {
        int grow = row0 + r + i;
        #pragma unroll
        for (int j = 0; j < 8; j++) {
            int gcol = col0 + c + j;
            float v = acc[i][j];
            if (EPI == EPI_DECAY) {
                int diff = grow - gcol;
                v = (diff < 0) ? 0.f : v * expf(lg * (float)diff);
            } else if (EPI == EPI_RES) {
                v += res[(size_t)grow * ldc + gcol];
            } else if (EPI == EPI_BIAS_GELU) {
                v += bias[gcol];
                float u3 = v * v * v;
                v = 0.5f * v * (1.f + tanhf(0.7978845608f * (v + 0.044715f * u3)));
            } else if (EPI == EPI_BIAS_RES) {
                v += bias[gcol] + res[(size_t)grow * ldc + gcol];
            }
            C[(size_t)grow * ldc + gcol] = v;
        }
    }
}

// ---------------------------------------------------------------------------
extern "C" void kernel_launch(void* const* d_in, const int* in_sizes, int n_in,
                              void* d_out, int out_size) {
    const float* x   = (const float*)d_in[0];
    const float* Wq  = (const float*)d_in[1];
    const float* Wk  = (const float*)d_in[2];
    const float* Wv  = (const float*)d_in[3];
    const float* Wg  = (const float*)d_in[4];
    const float* Wo  = (const float*)d_in[5];
    const float* gng = (const float*)d_in[6];
    const float* gnb = (const float*)d_in[7];
    const float* W1  = (const float*)d_in[8];
    const float* b1  = (const float*)d_in[9];
    const float* W2  = (const float*)d_in[10];
    const float* b2  = (const float*)d_in[11];
    const float* lng = (const float*)d_in[12];
    const float* lnb = (const float*)d_in[13];
    float* out = (float*)d_out;

    float *xn, *q, *k, *v, *gt, *y, *zb, *ret, *x1, *sc, *ffn;
    cudaGetSymbolAddress((void**)&xn,  g_xn);
    cudaGetSymbolAddress((void**)&q,   g_q);
    cudaGetSymbolAddress((void**)&k,   g_k);
    cudaGetSymbolAddress((void**)&v,   g_v);
    cudaGetSymbolAddress((void**)&gt,  g_gt);
    cudaGetSymbolAddress((void**)&y,   g_y);
    cudaGetSymbolAddress((void**)&zb,  g_z);
    cudaGetSymbolAddress((void**)&ret, g_ret);
    cudaGetSymbolAddress((void**)&x1,  g_x1);
    cudaGetSymbolAddress((void**)&sc,  g_sc);
    cudaGetSymbolAddress((void**)&ffn, g_ffn);

    dim3 blk(256);
    dim3 gp(Hdim / BN, MT / BM, 1);          // 16 x 32

    for (int i = 0; i < LAYERS; i++) {
        const float* xin = (i == 0) ? x : x1;
        const size_t wOff = (size_t)i * Hdim * Hdim;

        // xn = LN(xin)
        ln_k<<<MT, blk>>>(xin, lng, lnb, xn);

        // q,k,v,gate projections
        gemm_k<false, EPI_NONE, false><<<gp, blk>>>(xn, Wq + wOff, q,  MT, Hdim, Hdim,
            Hdim, Hdim, Hdim, 0, 0, 0, 0, 0, 0, 1, nullptr, nullptr);
        gemm_k<false, EPI_NONE, false><<<gp, blk>>>(xn, Wk + wOff, k,  MT, Hdim, Hdim,
            Hdim, Hdim, Hdim, 0, 0, 0, 0, 0, 0, 1, nullptr, nullptr);
        gemm_k<false, EPI_NONE, false><<<gp, blk>>>(xn, Wv + wOff, v,  MT, Hdim, Hdim,
            Hdim, Hdim, Hdim, 0, 0, 0, 0, 0, 0, 1, nullptr, nullptr);
        gemm_k<false, EPI_NONE, false><<<gp, blk>>>(xn, Wg + wOff, gt, MT, Hdim, Hdim,
            Hdim, Hdim, Hdim, 0, 0, 0, 0, 0, 0, 1, nullptr, nullptr);

        // scores[b,h] = (q_slice @ k_slice^T) * D   (batched over 32 (b,h))
        dim3 gs(Sn / BN, Sn / BM, Bn * NH);  // 8 x 8 x 32
        gemm_k<true, EPI_DECAY, false><<<gs, blk>>>(q, k, sc, Sn, Sn, HD,
            Hdim, Hdim, Sn,
            (long long)Sn * Hdim, (long long)HD,
            (long long)Sn * Hdim, (long long)HD,
            (long long)NH * Sn * Sn, (long long)Sn * Sn, NH, nullptr, nullptr);

        // y[b,h] = scores @ v_slice  (K clamped to causal extent)
        dim3 gy(HD / BN, Sn / BM, Bn * NH);  // 2 x 8 x 32
        gemm_k<false, EPI_NONE, true><<<gy, blk>>>(sc, v, y, Sn, HD, Sn,
            Sn, Hdim, Hdim,
            (long long)NH * Sn * Sn, (long long)Sn * Sn,
            (long long)Sn * Hdim, (long long)HD,
            (long long)Sn * Hdim, (long long)HD, NH, nullptr, nullptr);

        // z = silu(gate) * GroupNorm(y)
        gn_gate_k<<<MT * NH, blk>>>(y, gt, gng + (size_t)i * Hdim,
                                    gnb + (size_t)i * Hdim, zb);

        // ret = z @ Wo + xin
        gemm_k<false, EPI_RES, false><<<gp, blk>>>(zb, Wo + wOff, ret, MT, Hdim, Hdim,
            Hdim, Hdim, Hdim, 0, 0, 0, 0, 0, 0, 1, nullptr, xin);

        // xn = LN(ret)
        ln_k<<<MT, blk>>>(ret, lng, lnb, xn);

        // ffn = gelu(xn @ W1 + b1)
        dim3 g1(FFdim / BN, MT / BM, 1);     // 64 x 32
        gemm_k<false, EPI_BIAS_GELU, false><<<g1, blk>>>(xn, W1 + (size_t)i * Hdim * FFdim,
            ffn, MT, FFdim, Hdim, Hdim, FFdim, FFdim,
            0, 0, 0, 0, 0, 0, 1, b1 + (size_t)i * FFdim, nullptr);

        // x_next = ffn @ W2 + b2 + ret
        float* dst = (i == LAYERS - 1) ? out : x1;
        gemm_k<false, EPI_BIAS_RES, false><<<gp, blk>>>(ffn, W2 + (size_t)i * FFdim * Hdim,
            dst, MT, Hdim, FFdim, FFdim, Hdim, Hdim,
            0, 0, 0, 0, 0, 0, 1, b2 + (size_t)i * Hdim, ret);
    }
}

// round 2
// speedup vs baseline: 2.3075x; 2.3075x over previous
#include <cuda_runtime.h>
#include <math.h>
#include <stdint.h>

// ---------------------------------------------------------------------------
// RetentiveNetwork forward — TF32 tensor-core GEMMs (mma.sync.m16n8k8).
// L=2, H=2048, HEADS=8, HEAD=256, FF=8192, B=4, S=1024.
// ---------------------------------------------------------------------------

constexpr int LAYERS = 2;
constexpr int Hdim   = 2048;
constexpr int NH     = 8;
constexpr int HD     = 256;
constexpr int FFdim  = 8192;
constexpr int Bn     = 4;
constexpr int Sn     = 1024;
constexpr int MT     = Bn * Sn;

// ---------------- scratch ---------------------------------------------------
__device__ float g_xn [MT * Hdim];
__device__ float g_q  [MT * Hdim];
__device__ float g_k  [MT * Hdim];
__device__ float g_v  [MT * Hdim];
__device__ float g_gt [MT * Hdim];
__device__ float g_y  [MT * Hdim];
__device__ float g_z  [MT * Hdim];
__device__ float g_ret[MT * Hdim];
__device__ float g_x1 [MT * Hdim];
__device__ float g_sc [(size_t)Bn * NH * Sn * Sn];
__device__ float g_ffn[(size_t)MT * FFdim];

// ---------------- helpers ---------------------------------------------------
__device__ __forceinline__ float blockReduce(float v, float* sh) {
    int lane = threadIdx.x & 31, w = threadIdx.x >> 5;
    #pragma unroll
    for (int o = 16; o; o >>= 1) v += __shfl_xor_sync(0xffffffffu, v, o);
    if (lane == 0) sh[w] = v;
    __syncthreads();
    if (w == 0) {
        float r = (lane < (int)(blockDim.x >> 5)) ? sh[lane] : 0.f;
        #pragma unroll
        for (int o = 4; o; o >>= 1) r += __shfl_xor_sync(0xffffffffu, r, o);
        if (lane == 0) sh[0] = r;
    }
    __syncthreads();
    float res = sh[0];
    __syncthreads();
    return res;
}

__device__ __forceinline__ uint32_t f2tf(float x) {
    uint32_t u;
    asm("cvt.rna.tf32.f32 %0, %1;" : "=r"(u) : "f"(x));
    return u;
}

__device__ __forceinline__ void mma_tf32(float* c, const uint32_t* a, const uint32_t* b) {
    asm volatile(
        "mma.sync.aligned.m16n8k8.row.col.f32.tf32.tf32.f32 "
        "{%0,%1,%2,%3}, {%4,%5,%6,%7}, {%8,%9}, {%0,%1,%2,%3};"
        : "+f"(c[0]), "+f"(c[1]), "+f"(c[2]), "+f"(c[3])
        : "r"(a[0]), "r"(a[1]), "r"(a[2]), "r"(a[3]), "r"(b[0]), "r"(b[1]));
}

// ---------------- LayerNorm -------------------------------------------------
__global__ void ln_k(const float* __restrict__ x, const float* __restrict__ g,
                     const float* __restrict__ b, float* __restrict__ o) {
    __shared__ float sh[8];
    int tok = blockIdx.x;
    const float* xp = x + (size_t)tok * Hdim;
    float* op = o + (size_t)tok * Hdim;
    int t = threadIdx.x;
    float v[8];
    float s = 0.f;
    #pragma unroll
    for (int i = 0; i < 8; i++) { v[i] = xp[t + 256 * i]; s += v[i]; }
    float mu = blockReduce(s, sh) * (1.f / Hdim);
    float ss = 0.f;
    #pragma unroll
    for (int i = 0; i < 8; i++) { float d = v[i] - mu; ss += d * d; }
    float var = blockReduce(ss, sh) * (1.f / Hdim);
    float rs = rsqrtf(var + 1e-5f);
    #pragma unroll
    for (int i = 0; i < 8; i++) {
        int c = t + 256 * i;
        op[c] = (v[i] - mu) * rs * g[c] + b[c];
    }
}

// ---------------- GroupNorm + SiLU gate ------------------------------------
__global__ void gn_gate_k(const float* __restrict__ y, const float* __restrict__ gate,
                          const float* __restrict__ gg, const float* __restrict__ gb,
                          float* __restrict__ z) {
    __shared__ float sh[8];
    int grp = blockIdx.x;
    int h = grp & (NH - 1);
    size_t base = (size_t)(grp >> 3) * Hdim + (size_t)h * HD;
    int t = threadIdx.x;
    float val = y[base + t];
    float mu = blockReduce(val, sh) * (1.f / HD);
    float d = val - mu;
    float var = blockReduce(d * d, sh) * (1.f / HD);
    float rs = rsqrtf(var + 1e-5f);
    int c = h * HD + t;
    float gv = gate[base + t];
    float silu = gv / (1.f + expf(-gv));
    z[base + t] = (d * rs * gg[c] + gb[c]) * silu;
}

// ---------------- TF32 tensor-core GEMM -------------------------------------
// CTA tile 128x128, K-step 16. 8 warps, each 32(m) x 64(n):
//   warp -> 2 m-tiles (m16) x 8 n-tiles (n8), 16 mma per k8-step.
// Smem fragment-major layout: As[buf][kk][mtile][reg][33], Bs[buf][kk][ntile][reg][33].
// With the thread mappings below, both scatter-stores and fragment loads are
// bank-conflict-free (the *33 pad spreads tiles across all 32 banks).
constexpr int BM = 128, BN = 128, BK = 16;

enum { EPI_NONE = 0, EPI_DECAY = 1, EPI_RES = 2, EPI_BIAS_GELU = 3, EPI_BIAS_RES = 4 };

template<bool TRANSB, int EPI, bool TRILA>
__global__ void __launch_bounds__(256, 2)
gemm_tc(const float* __restrict__ A, const float* __restrict__ Bm, float* __restrict__ C,
        int M, int N, int K, int lda, int ldb, int ldc,
        long long sAb, long long sAh, long long sBb, long long sBh,
        long long sCb, long long sCh, int ZD,
        const float* __restrict__ bias, const float* __restrict__ res)
{
    __shared__ float As[2][2][8][4][33];
    __shared__ float Bs[2][2][16][2][33];
    __shared__ float dtab[256];

    int t  = threadIdx.x;
    int ln = t & 31;
    int w  = t >> 5;
    int wm = w >> 1;          // 0..3, m offset wm*32
    int wn = w & 1;           // 0..1, n offset wn*64

    int row0 = blockIdx.y * BM;
    int col0 = blockIdx.x * BN;
    int z = blockIdx.z;
    int hh = z % ZD;
    long long bb = z / ZD;
    A  += bb * sAb + (long long)hh * sAh;
    Bm += bb * sBb + (long long)hh * sBh;
    C  += bb * sCb + (long long)hh * sCh;

    // Causal: score blocks strictly above the diagonal are zero — skip compute.
    if (EPI == EPI_DECAY && row0 + BM <= col0) {
        float2 zz = make_float2(0.f, 0.f);
        #pragma unroll
        for (int mt = 0; mt < 2; mt++) {
            int r0 = row0 + wm * 32 + mt * 16 + (ln >> 2);
            #pragma unroll
            for (int nt = 0; nt < 8; nt++) {
                int cc = col0 + wn * 64 + nt * 8 + (ln & 3) * 2;
                *(float2*)&C[(size_t)r0 * ldc + cc]       = zz;
                *(float2*)&C[(size_t)(r0 + 8) * ldc + cc] = zz;
            }
        }
        return;
    }

    int Kend = TRILA ? min(K, row0 + BM) : K;
    int nk = Kend / BK;

    // --- gmem load pointers ---
    // A: 128 rows x 16 cols; thread t loads (row=t>>1, kc=(t&1)*4) and (+8 cols).
    const float* Ap = A + (size_t)(row0 + (t >> 1)) * lda + ((t & 1) * 4);
    const float* Bp;
    if (TRANSB) {
        // B is [N,K] row-major: same pattern as A along N.
        Bp = Bm + (size_t)(col0 + (t >> 1)) * ldb + ((t & 1) * 4);
    } else {
        // B is [K,N] row-major: 16 k-rows x 128 n-cols; (k=t>>4, n0=(t&15)*4) and (+64 cols).
        Bp = Bm + (size_t)(t >> 4) * ldb + col0 + ((t & 15) * 4);
    }

    // --- smem scatter-store helpers (convert to tf32 on the way in) ---
    auto stA = [&](int buf, float4 v, int second) {
        int ar = t >> 1;
        int kc = (t & 1) * 4 + second * 8;
        int kk = kc >> 3, hi = (kc >> 2) & 1;
        int mt = ar >> 4, lr = ar & 7, ib = (ar >> 3) & 1;
        int reg = hi * 2 + ib;
        float* p = &As[buf][kk][mt][reg][lr * 4];
        p[0] = __uint_as_float(f2tf(v.x));
        p[1] = __uint_as_float(f2tf(v.y));
        p[2] = __uint_as_float(f2tf(v.z));
        p[3] = __uint_as_float(f2tf(v.w));
    };
    auto stB = [&](int buf, float4 v, int second) {
        if (TRANSB) {
            int n  = t >> 1;
            int kc = (t & 1) * 4 + second * 8;
            int kk = kc >> 3, reg = (kc >> 2) & 1, nt = n >> 3;
            float* p = &Bs[buf][kk][nt][reg][(n & 7) * 4];
            p[0] = __uint_as_float(f2tf(v.x));
            p[1] = __uint_as_float(f2tf(v.y));
            p[2] = __uint_as_float(f2tf(v.z));
            p[3] = __uint_as_float(f2tf(v.w));
        } else {
            int k  = t >> 4;
            int n0 = (t & 15) * 4 + second * 64;
            int kk = k >> 3, reg = (k >> 2) & 1, k3 = k & 3;
            float vv[4] = {v.x, v.y, v.z, v.w};
            #pragma unroll
            for (int j = 0; j < 4; j++) {
                int n = n0 + j;
                Bs[buf][kk][n >> 3][reg][(n & 7) * 4 + k3] = __uint_as_float(f2tf(vv[j]));
            }
        }
    };

    // --- prologue ---
    float4 ra0 = *(const float4*)Ap;
    float4 ra1 = *(const float4*)(Ap + 8);
    float4 rb0 = *(const float4*)Bp;
    float4 rb1 = TRANSB ? *(const float4*)(Bp + 8) : *(const float4*)(Bp + 64);
    stA(0, ra0, 0); stA(0, ra1, 1);
    stB(0, rb0, 0); stB(0, rb1, 1);
    __syncthreads();

    float acc[2][8][4];
    #pragma unroll
    for (int mt = 0; mt < 2; mt++)
        #pragma unroll
        for (int nt = 0; nt < 8; nt++)
            #pragma unroll
            for (int i = 0; i < 4; i++) acc[mt][nt][i] = 0.f;

    for (int kt = 0; kt < nk; kt++) {
        int cur = kt & 1;
        if (kt + 1 < nk) {
            const float* Apn = Ap + (size_t)(kt + 1) * BK;
            ra0 = *(const float4*)Apn;
            ra1 = *(const float4*)(Apn + 8);
            if (TRANSB) {
                const float* Bpn = Bp + (size_t)(kt + 1) * BK;
                rb0 = *(const float4*)Bpn;
                rb1 = *(const float4*)(Bpn + 8);
            } else {
                const float* Bpn = Bp + (size_t)(kt + 1) * BK * ldb;
                rb0 = *(const float4*)Bpn;
                rb1 = *(const float4*)(Bpn + 64);
            }
        }
        #pragma unroll
        for (int kk = 0; kk < 2; kk++) {
            uint32_t af[2][4], bf[8][2];
            #pragma unroll
            for (int mt = 0; mt < 2; mt++)
                #pragma unroll
                for (int i = 0; i < 4; i++)
                    af[mt][i] = __float_as_uint(As[cur][kk][wm * 2 + mt][i][ln]);
            #pragma unroll
            for (int nt = 0; nt < 8; nt++)
                #pragma unroll
                for (int i = 0; i < 2; i++)
                    bf[nt][i] = __float_as_uint(Bs[cur][kk][wn * 8 + nt][i][ln]);
            #pragma unroll
            for (int mt = 0; mt < 2; mt++)
                #pragma unroll
                for (int nt = 0; nt < 8; nt++)
                    mma_tf32(acc[mt][nt], af[mt], bf[nt]);
        }
        if (kt + 1 < nk) {
            int nxt = cur ^ 1;
            stA(nxt, ra0, 0); stA(nxt, ra1, 1);
            stB(nxt, rb0, 0); stB(nxt, rb1, 1);
        }
        __syncthreads();
    }

    // --- epilogue ---
    int dmin = 0;
    if (EPI == EPI_DECAY) {
        // gamma_h = 1 - exp(linspace(ln(1/32), ln(1/512), 8))[h]
        float gamma = 1.f - expf(-(3.46573590f + 0.396084103f * (float)hh));
        float lg = logf(gamma);
        dmin = row0 - col0 - 127;
        if (t < 256) {
            int d = dmin + t;
            dtab[t] = (d < 0) ? 0.f : expf(lg * (float)d);
        }
        __syncthreads();
    }

    #pragma unroll
    for (int mt = 0; mt < 2; mt++) {
        int r0 = row0 + wm * 32 + mt * 16 + (ln >> 2);
        #pragma unroll
        for (int nt = 0; nt < 8; nt++) {
            int cc = col0 + wn * 64 + nt * 8 + (ln & 3) * 2;
            #pragma unroll
            for (int half = 0; half < 2; half++) {
                int grow = r0 + half * 8;
                float v0 = acc[mt][nt][half * 2 + 0];
                float v1 = acc[mt][nt][half * 2 + 1];
                if (EPI == EPI_DECAY) {
                    int d0 = grow - cc, d1 = d0 - 1;
                    v0 = (d0 < 0) ? 0.f : v0 * dtab[d0 - dmin];
                    v1 = (d1 < 0) ? 0.f : v1 * dtab[d1 - dmin];
                } else if (EPI == EPI_RES) {
                    v0 += res[(size_t)grow * ldc + cc];
                    v1 += res[(size_t)grow * ldc + cc + 1];
                } else if (EPI == EPI_BIAS_GELU) {
                    v0 += bias[cc];
                    v1 += bias[cc + 1];
                    float u0 = v0, u1 = v1;
                    v0 = 0.5f * u0 * (1.f + tanhf(0.7978845608f * (u0 + 0.044715f * u0 * u0 * u0)));
                    v1 = 0.5f * u1 * (1.f + tanhf(0.7978845608f * (u1 + 0.044715f * u1 * u1 * u1)));
                } else if (EPI == EPI_BIAS_RES) {
                    v0 += bias[cc]     + res[(size_t)grow * ldc + cc];
                    v1 += bias[cc + 1] + res[(size_t)grow * ldc + cc + 1];
                }
                float2 o2 = make_float2(v0, v1);
                *(float2*)&C[(size_t)grow * ldc + cc] = o2;
            }
        }
    }
}

// ---------------------------------------------------------------------------
extern "C" void kernel_launch(void* const* d_in, const int* in_sizes, int n_in,
                              void* d_out, int out_size) {
    const float* x   = (const float*)d_in[0];
    const float* Wq  = (const float*)d_in[1];
    const float* Wk  = (const float*)d_in[2];
    const float* Wv  = (const float*)d_in[3];
    const float* Wg  = (const float*)d_in[4];
    const float* Wo  = (const float*)d_in[5];
    const float* gng = (const float*)d_in[6];
    const float* gnb = (const float*)d_in[7];
    const float* W1  = (const float*)d_in[8];
    const float* b1  = (const float*)d_in[9];
    const float* W2  = (const float*)d_in[10];
    const float* b2  = (const float*)d_in[11];
    const float* lng = (const float*)d_in[12];
    const float* lnb = (const float*)d_in[13];
    float* out = (float*)d_out;

    float *xn, *q, *k, *v, *gt, *y, *zb, *ret, *x1, *sc, *ffn;
    cudaGetSymbolAddress((void**)&xn,  g_xn);
    cudaGetSymbolAddress((void**)&q,   g_q);
    cudaGetSymbolAddress((void**)&k,   g_k);
    cudaGetSymbolAddress((void**)&v,   g_v);
    cudaGetSymbolAddress((void**)&gt,  g_gt);
    cudaGetSymbolAddress((void**)&y,   g_y);
    cudaGetSymbolAddress((void**)&zb,  g_z);
    cudaGetSymbolAddress((void**)&ret, g_ret);
    cudaGetSymbolAddress((void**)&x1,  g_x1);
    cudaGetSymbolAddress((void**)&sc,  g_sc);
    cudaGetSymbolAddress((void**)&ffn, g_ffn);

    dim3 blk(256);
    dim3 gp(Hdim / BN, MT / BM, 1);

    for (int i = 0; i < LAYERS; i++) {
        const float* xin = (i == 0) ? x : x1;
        const size_t wOff = (size_t)i * Hdim * Hdim;

        ln_k<<<MT, blk>>>(xin, lng, lnb, xn);

        gemm_tc<false, EPI_NONE, false><<<gp, blk>>>(xn, Wq + wOff, q,  MT, Hdim, Hdim,
            Hdim, Hdim, Hdim, 0, 0, 0, 0, 0, 0, 1, nullptr, nullptr);
        gemm_tc<false, EPI_NONE, false><<<gp, blk>>>(xn, Wk + wOff, k,  MT, Hdim, Hdim,
            Hdim, Hdim, Hdim, 0, 0, 0, 0, 0, 0, 1, nullptr, nullptr);
        gemm_tc<false, EPI_NONE, false><<<gp, blk>>>(xn, Wv + wOff, v,  MT, Hdim, Hdim,
            Hdim, Hdim, Hdim, 0, 0, 0, 0, 0, 0, 1, nullptr, nullptr);
        gemm_tc<false, EPI_NONE, false><<<gp, blk>>>(xn, Wg + wOff, gt, MT, Hdim, Hdim,
            Hdim, Hdim, Hdim, 0, 0, 0, 0, 0, 0, 1, nullptr, nullptr);

        // scores = (q @ k^T) * D
        dim3 gs(Sn / BN, Sn / BM, Bn * NH);
        gemm_tc<true, EPI_DECAY, false><<<gs, blk>>>(q, k, sc, Sn, Sn, HD,
            Hdim, Hdim, Sn,
            (long long)Sn * Hdim, (long long)HD,
            (long long)Sn * Hdim, (long long)HD,
            (long long)NH * Sn * Sn, (long long)Sn * Sn, NH, nullptr, nullptr);

        // y = scores @ v  (K clamped to causal extent)
        dim3 gy(HD / BN, Sn / BM, Bn * NH);
        gemm_tc<false, EPI_NONE, true><<<gy, blk>>>(sc, v, y, Sn, HD, Sn,
            Sn, Hdim, Hdim,
            (long long)NH * Sn * Sn, (long long)Sn * Sn,
            (long long)Sn * Hdim, (long long)HD,
            (long long)Sn * Hdim, (long long)HD, NH, nullptr, nullptr);

        gn_gate_k<<<MT * NH, blk>>>(y, gt, gng + (size_t)i * Hdim,
                                    gnb + (size_t)i * Hdim, zb);

        gemm_tc<false, EPI_RES, false><<<gp, blk>>>(zb, Wo + wOff, ret, MT, Hdim, Hdim,
            Hdim, Hdim, Hdim, 0, 0, 0, 0, 0, 0, 1, nullptr, xin);

        ln_k<<<MT, blk>>>(ret, lng, lnb, xn);

        dim3 g1(FFdim / BN, MT / BM, 1);
        gemm_tc<false, EPI_BIAS_GELU, false><<<g1, blk>>>(xn, W1 + (size_t)i * Hdim * FFdim,
            ffn, MT, FFdim, Hdim, Hdim, FFdim, FFdim,
            0, 0, 0, 0, 0, 0, 1, b1 + (size_t)i * FFdim, nullptr);

        float* dst = (i == LAYERS - 1) ? out : x1;
        gemm_tc<false, EPI_BIAS_RES, false><<<gp, blk>>>(ffn, W2 + (size_t)i * FFdim * Hdim,
            dst, MT, Hdim, FFdim, FFdim, Hdim, Hdim,
            0, 0, 0, 0, 0, 0, 1, b2 + (size_t)i * Hdim, ret);
    }
}

// round 4
// speedup vs baseline: 3.3010x; 1.4306x over previous
#include <cuda_runtime.h>
#include <math.h>
#include <stdint.h>

// ---------------------------------------------------------------------------
// RetentiveNetwork forward — TF32 mma.sync TN GEMMs with cp.async + ldmatrix.
// L=2, H=2048, HEADS=8, HEAD=256, FF=8192, B=4, S=1024.
// All GEMM inputs are pre-rounded to tf32 at producers; all GEMMs are TN
// (A [M,K] row-major, B [N,K] row-major; weights pre-transposed once).
// ---------------------------------------------------------------------------

constexpr int LAYERS = 2;
constexpr int Hdim   = 2048;
constexpr int NH     = 8;
constexpr int HD     = 256;
constexpr int FFdim  = 8192;
constexpr int Bn     = 4;
constexpr int Sn     = 1024;
constexpr int MT     = Bn * Sn;

// ---------------- scratch ---------------------------------------------------
__device__ float g_xn [MT * Hdim];
__device__ float g_q  [MT * Hdim];
__device__ float g_k  [MT * Hdim];
__device__ float g_vT [MT * Hdim];     // [b][channel][s]
__device__ float g_gt [MT * Hdim];
__device__ float g_y  [MT * Hdim];
__device__ float g_z  [MT * Hdim];
__device__ float g_ret[MT * Hdim];
__device__ float g_x1 [MT * Hdim];
__device__ float g_sc [(size_t)Bn * NH * Sn * Sn];
__device__ float g_ffn[(size_t)MT * FFdim];
// transposed+rounded weights: per layer 52M floats:
// WqT 0, WkT 4M, WvT 8M, WgT 12M, WoT 16M, W1T 20M(16M elems), W2T 36M(16M elems)
constexpr size_t WT_L = (size_t)52 * 1024 * 1024;
__device__ float g_wt[(size_t)LAYERS * WT_L];

// ---------------- helpers ---------------------------------------------------
__device__ __forceinline__ float blockReduce(float v, float* sh) {
    int lane = threadIdx.x & 31, w = threadIdx.x >> 5;
    #pragma unroll
    for (int o = 16; o; o >>= 1) v += __shfl_xor_sync(0xffffffffu, v, o);
    if (lane == 0) sh[w] = v;
    __syncthreads();
    if (w == 0) {
        float r = (lane < (int)(blockDim.x >> 5)) ? sh[lane] : 0.f;
        #pragma unroll
        for (int o = 4; o; o >>= 1) r += __shfl_xor_sync(0xffffffffu, r, o);
        if (lane == 0) sh[0] = r;
    }
    __syncthreads();
    float res = sh[0];
    __syncthreads();
    return res;
}

__device__ __forceinline__ uint32_t f2tf(float x) {
    uint32_t u;
    asm("cvt.rna.tf32.f32 %0, %1;" : "=r"(u) : "f"(x));
    return u;
}
__device__ __forceinline__ float rnd(float x) { return __uint_as_float(f2tf(x)); }

__device__ __forceinline__ void mma_tf32(float* c, const uint32_t* a, const uint32_t* b) {
    asm volatile(
        "mma.sync.aligned.m16n8k8.row.col.f32.tf32.tf32.f32 "
        "{%0,%1,%2,%3}, {%4,%5,%6,%7}, {%8,%9}, {%0,%1,%2,%3};"
        : "+f"(c[0]), "+f"(c[1]), "+f"(c[2]), "+f"(c[3])
        : "r"(a[0]), "r"(a[1]), "r"(a[2]), "r"(a[3]), "r"(b[0]), "r"(b[1]));
}

__device__ __forceinline__ void ldsm4(uint32_t* r, uint32_t addr) {
    asm volatile("ldmatrix.sync.aligned.m8n8.x4.shared.b16 {%0,%1,%2,%3}, [%4];"
        : "=r"(r[0]), "=r"(r[1]), "=r"(r[2]), "=r"(r[3]) : "r"(addr));
}

__device__ __forceinline__ void cp16(uint32_t dst, const void* src) {
    asm volatile("cp.async.cg.shared.global [%0], [%1], 16;" :: "r"(dst), "l"(src));
}

// ---------------- LayerNorm (rounds output to tf32) -------------------------
__global__ void ln_k(const float* __restrict__ x, const float* __restrict__ g,
                     const float* __restrict__ b, float* __restrict__ o) {
    __shared__ float sh[8];
    int tok = blockIdx.x;
    const float* xp = x + (size_t)tok * Hdim;
    float* op = o + (size_t)tok * Hdim;
    int t = threadIdx.x;
    float v[8];
    float s = 0.f;
    #pragma unroll
    for (int i = 0; i < 8; i++) { v[i] = xp[t + 256 * i]; s += v[i]; }
    float mu = blockReduce(s, sh) * (1.f / Hdim);
    float ss = 0.f;
    #pragma unroll
    for (int i = 0; i < 8; i++) { float d = v[i] - mu; ss += d * d; }
    float var = blockReduce(ss, sh) * (1.f / Hdim);
    float rs = rsqrtf(var + 1e-5f);
    #pragma unroll
    for (int i = 0; i < 8; i++) {
        int c = t + 256 * i;
        op[c] = rnd((v[i] - mu) * rs * g[c] + b[c]);
    }
}

// ---------------- GroupNorm + SiLU gate (rounds output) ---------------------
__global__ void gn_gate_k(const float* __restrict__ y, const float* __restrict__ gate,
                          const float* __restrict__ gg, const float* __restrict__ gb,
                          float* __restrict__ z) {
    __shared__ float sh[8];
    int grp = blockIdx.x;
    int h = grp & (NH - 1);
    size_t base = (size_t)(grp >> 3) * Hdim + (size_t)h * HD;
    int t = threadIdx.x;
    float val = y[base + t];
    float mu = blockReduce(val, sh) * (1.f / HD);
    float d = val - mu;
    float var = blockReduce(d * d, sh) * (1.f / HD);
    float rs = rsqrtf(var + 1e-5f);
    int c = h * HD + t;
    float gv = gate[base + t];
    float silu = gv / (1.f + expf(-gv));
    z[base + t] = rnd((d * rs * gg[c] + gb[c]) * silu);
}

// ---------------- weight transpose + tf32 round: W[K,N] -> WT[N,K] ----------
__global__ void wt_k(const float* __restrict__ W, float* __restrict__ WT, int K, int N) {
    __shared__ float tile[32][33];
    int tx = threadIdx.x & 31, ty = threadIdx.x >> 5;
    int k0 = blockIdx.y * 32, n0 = blockIdx.x * 32;
    #pragma unroll
    for (int j = 0; j < 32; j += 8)
        tile[ty + j][tx] = W[(size_t)(k0 + ty + j) * N + n0 + tx];
    __syncthreads();
    #pragma unroll
    for (int j = 0; j < 32; j += 8)
        WT[(size_t)(n0 + ty + j) * K + k0 + tx] = rnd(tile[tx][ty + j]);
}

// ---------------- TN TF32 GEMM: cp.async 4-stage + ldmatrix ------------------
// Tile 128x128, BK=16 (two k8 steps/stage). 8 warps: 4(m) x 2(n), each 32m x 64n.
// Smem row = 16 tf32 = 64B data + 16B pad (80B stride): conflict-free ldmatrix.
constexpr int BM = 128, BN = 128, BK = 16;
constexpr int STAGES  = 4;
constexpr int ROW_B   = 80;                         // bytes per smem row
constexpr int TILE_B  = 128 * ROW_B;                // 10240 B per operand tile
constexpr int STAGE_B = 2 * TILE_B;                 // 20480 B
constexpr int SMEM_B  = STAGES * STAGE_B + 1024;    // + decay table

enum { EPI_NONE = 0, EPI_DECAY = 1, EPI_RES = 2, EPI_BIAS_GELU = 3, EPI_BIAS_RES = 4 };

template<int EPI, bool TRILA, bool STORET, bool RND>
__global__ void __launch_bounds__(256, 2)
gemm_tc(const float* __restrict__ A, const float* __restrict__ Bm, float* __restrict__ C,
        int K, int lda, int ldb, int ldc,
        long long sAb, long long sAh, long long sBb, long long sBh,
        long long sCb, long long sCh, int ZD,
        const float* __restrict__ bias, const float* __restrict__ res)
{
    extern __shared__ float smem[];
    uint32_t sbase;
    asm("{ .reg .u64 t; cvta.to.shared.u64 t, %1; cvt.u32.u64 %0, t; }"
        : "=r"(sbase) : "l"(smem));
    float* dtab = smem + (STAGES * STAGE_B) / 4;

    int t  = threadIdx.x;
    int ln = t & 31;
    int w  = t >> 5;
    int wm = w >> 1;          // 0..3 -> m offset wm*32
    int wn = w & 1;           // 0..1 -> n offset wn*64

    int row0 = blockIdx.y * BM;
    int col0 = blockIdx.x * BN;
    int z = blockIdx.z;
    int hh = z % ZD;
    long long bb = z / ZD;
    A  += bb * sAb + (long long)hh * sAh;
    Bm += bb * sBb + (long long)hh * sBh;
    C  += bb * sCb + (long long)hh * sCh;

    // Causal: score blocks strictly above the diagonal are zero — skip compute.
    if (EPI == EPI_DECAY && row0 + BM <= col0) {
        float2 zz = make_float2(0.f, 0.f);
        #pragma unroll
        for (int mt = 0; mt < 2; mt++) {
            int r0 = row0 + wm * 32 + mt * 16 + (ln >> 2);
            #pragma unroll
            for (int nt = 0; nt < 8; nt++) {
                int cc = col0 + wn * 64 + nt * 8 + (ln & 3) * 2;
                *(float2*)&C[(size_t)r0 * ldc + cc]       = zz;
                *(float2*)&C[(size_t)(r0 + 8) * ldc + cc] = zz;
            }
        }
        return;
    }

    if (EPI == EPI_DECAY) {
        float gamma = 1.f - expf(-(3.46573590f + 0.396084103f * (float)hh));
        float lg = logf(gamma);
        int d = row0 - col0 - 127 + t;
        dtab[t] = (d < 0) ? 0.f : expf(lg * (float)d);
        // visibility established by the first __syncthreads in the main loop
    }

    int Kend = TRILA ? min(K, row0 + BM) : K;
    int nk = Kend / BK;

    const float* Ap0 = A  + (size_t)row0 * lda;
    const float* Bp0 = Bm + (size_t)col0 * ldb;
    int cRow = t >> 2, cC = t & 3;   // copy mapping: chunks t and t+256

    auto issue = [&](int s, int kt) {
        if (kt < nk) {
            uint32_t sa = sbase + s * STAGE_B;
            uint32_t sb = sa + TILE_B;
            #pragma unroll
            for (int i = 0; i < 2; i++) {
                int row = cRow + i * 64;
                cp16(sa + row * ROW_B + cC * 16,
                     Ap0 + (size_t)row * lda + kt * BK + cC * 4);
                cp16(sb + row * ROW_B + cC * 16,
                     Bp0 + (size_t)row * ldb + kt * BK + cC * 4);
            }
        }
        asm volatile("cp.async.commit_group;");
    };

    issue(0, 0); issue(1, 1); issue(2, 2);

    float acc[2][8][4];
    #pragma unroll
    for (int mt = 0; mt < 2; mt++)
        #pragma unroll
        for (int nt = 0; nt < 8; nt++)
            #pragma unroll
            for (int i = 0; i < 4; i++) acc[mt][nt][i] = 0.f;

    // ldmatrix per-lane address components
    int aR = wm * 32 + ((ln >> 3) & 1) * 8 + (ln & 7);
    int aH = ln >> 4;                       // k-half: 0,0,1,1 per lane octet
    int bR = wn * 64 + ((ln >> 4) & 1) * 8 + (ln & 7);
    int bH = (ln >> 3) & 1;                 // k-half: 0,1,0,1 per lane octet

    for (int kt = 0; kt < nk; kt++) {
        asm volatile("cp.async.wait_group 2;");
        __syncthreads();
        issue((kt + 3) & 3, kt + 3);

        uint32_t sa = sbase + (kt & 3) * STAGE_B;
        uint32_t sb = sa + TILE_B;
        #pragma unroll
        for (int kk = 0; kk < 2; kk++) {
            uint32_t af[2][4];
            #pragma unroll
            for (int mt = 0; mt < 2; mt++)
                ldsm4(af[mt], sa + (aR + mt * 16) * ROW_B + (kk * 2 + aH) * 16);
            uint32_t bf[8][2];
            #pragma unroll
            for (int pp = 0; pp < 4; pp++) {
                uint32_t tmp[4];
                ldsm4(tmp, sb + (bR + pp * 16) * ROW_B + (kk * 2 + bH) * 16);
                bf[2 * pp][0]     = tmp[0];
                bf[2 * pp][1]     = tmp[1];
                bf[2 * pp + 1][0] = tmp[2];
                bf[2 * pp + 1][1] = tmp[3];
            }
            #pragma unroll
            for (int mt = 0; mt < 2; mt++)
                #pragma unroll
                for (int nt = 0; nt < 8; nt++)
                    mma_tf32(acc[mt][nt], af[mt], bf[nt]);
        }
    }

    // --- epilogue ---
    int dmin = row0 - col0 - 127;
    #pragma unroll
    for (int mt = 0; mt < 2; mt++) {
        int r0 = row0 + wm * 32 + mt * 16 + (ln >> 2);
        #pragma unroll
        for (int nt = 0; nt < 8; nt++) {
            int cc = col0 + wn * 64 + nt * 8 + (ln & 3) * 2;
            #pragma unroll
            for (int half = 0; half < 2; half++) {
                int grow = r0 + half * 8;
                float v0 = acc[mt][nt][half * 2 + 0];
                float v1 = acc[mt][nt][half * 2 + 1];
                if (EPI == EPI_DECAY) {
                    int d0 = grow - cc, d1 = d0 - 1;
                    v0 = (d0 < 0) ? 0.f : v0 * dtab[d0 - dmin];
                    v1 = (d1 < 0) ? 0.f : v1 * dtab[d1 - dmin];
                } else if (EPI == EPI_RES) {
                    v0 += res[(size_t)grow * ldc + cc];
                    v1 += res[(size_t)grow * ldc + cc + 1];
                } else if (EPI == EPI_BIAS_GELU) {
                    v0 += bias[cc];
                    v1 += bias[cc + 1];
                    float u0 = v0, u1 = v1;
                    v0 = 0.5f * u0 * (1.f + tanhf(0.7978845608f * (u0 + 0.044715f * u0 * u0 * u0)));
                    v1 = 0.5f * u1 * (1.f + tanhf(0.7978845608f * (u1 + 0.044715f * u1 * u1 * u1)));
                } else if (EPI == EPI_BIAS_RES) {
                    v0 += bias[cc]     + res[(size_t)grow * ldc + cc];
                    v1 += bias[cc + 1] + res[(size_t)grow * ldc + cc + 1];
                }
                if (RND) { v0 = rnd(v0); v1 = rnd(v1); }
                if (STORET) {
                    // vT[b][channel][s]: b = grow>>10, s = grow&1023, channel = cc
                    size_t vb = ((size_t)(grow >> 10) << 21) + (size_t)(grow & 1023);
                    C[vb + (size_t)cc * 1024]       = v0;
                    C[vb + (size_t)(cc + 1) * 1024] = v1;
                } else {
                    *(float2*)&C[(size_t)grow * ldc + cc] = make_float2(v0, v1);
                }
            }
        }
    }
}

// ---------------------------------------------------------------------------
template<int EPI, bool TRILA, bool STORET, bool RND>
static void set_smem() {
    cudaFuncSetAttribute(gemm_tc<EPI, TRILA, STORET, RND>,
                         cudaFuncAttributeMaxDynamicSharedMemorySize, SMEM_B);
}

extern "C" void kernel_launch(void* const* d_in, const int* in_sizes, int n_in,
                              void* d_out, int out_size) {
    const float* x   = (const float*)d_in[0];
    const float* Wq  = (const float*)d_in[1];
    const float* Wk  = (const float*)d_in[2];
    const float* Wv  = (const float*)d_in[3];
    const float* Wg  = (const float*)d_in[4];
    const float* Wo  = (const float*)d_in[5];
    const float* gng = (const float*)d_in[6];
    const float* gnb = (const float*)d_in[7];
    const float* W1  = (const float*)d_in[8];
    const float* b1  = (const float*)d_in[9];
    const float* W2  = (const float*)d_in[10];
    const float* b2  = (const float*)d_in[11];
    const float* lng = (const float*)d_in[12];
    const float* lnb = (const float*)d_in[13];
    float* out = (float*)d_out;

    float *xn, *q, *k, *vT, *gt, *y, *zb, *ret, *x1, *sc, *ffn, *wt;
    cudaGetSymbolAddress((void**)&xn,  g_xn);
    cudaGetSymbolAddress((void**)&q,   g_q);
    cudaGetSymbolAddress((void**)&k,   g_k);
    cudaGetSymbolAddress((void**)&vT,  g_vT);
    cudaGetSymbolAddress((void**)&gt,  g_gt);
    cudaGetSymbolAddress((void**)&y,   g_y);
    cudaGetSymbolAddress((void**)&zb,  g_z);
    cudaGetSymbolAddress((void**)&ret, g_ret);
    cudaGetSymbolAddress((void**)&x1,  g_x1);
    cudaGetSymbolAddress((void**)&sc,  g_sc);
    cudaGetSymbolAddress((void**)&ffn, g_ffn);
    cudaGetSymbolAddress((void**)&wt,  g_wt);

    set_smem<EPI_NONE,      false, false, true >();
    set_smem<EPI_NONE,      false, true,  true >();
    set_smem<EPI_NONE,      false, false, false>();
    set_smem<EPI_DECAY,     false, false, true >();
    set_smem<EPI_NONE,      true,  false, false>();
    set_smem<EPI_RES,       false, false, false>();
    set_smem<EPI_BIAS_GELU, false, false, true >();
    set_smem<EPI_BIAS_RES,  false, false, false>();

    dim3 blk(256);

    // --- transpose + round all weights into g_wt -----------------------------
    const size_t M4 = (size_t)4 * 1024 * 1024, M16 = (size_t)16 * 1024 * 1024;
    for (int i = 0; i < LAYERS; i++) {
        float* base = wt + (size_t)i * WT_L;
        const size_t wOff = (size_t)i * Hdim * Hdim;
        dim3 gH(Hdim / 32, Hdim / 32);
        wt_k<<<gH, blk>>>(Wq + wOff, base + 0 * M4, Hdim, Hdim);
        wt_k<<<gH, blk>>>(Wk + wOff, base + 1 * M4, Hdim, Hdim);
        wt_k<<<gH, blk>>>(Wv + wOff, base + 2 * M4, Hdim, Hdim);
        wt_k<<<gH, blk>>>(Wg + wOff, base + 3 * M4, Hdim, Hdim);
        wt_k<<<gH, blk>>>(Wo + wOff, base + 4 * M4, Hdim, Hdim);
        wt_k<<<dim3(FFdim / 32, Hdim / 32), blk>>>(W1 + (size_t)i * Hdim * FFdim,
                                                   base + 5 * M4, Hdim, FFdim);
        wt_k<<<dim3(Hdim / 32, FFdim / 32), blk>>>(W2 + (size_t)i * FFdim * Hdim,
                                                   base + 5 * M4 + M16, FFdim, Hdim);
    }

    dim3 gp(Hdim / BN, MT / BM, 1);

    for (int i = 0; i < LAYERS; i++) {
        const float* xin = (i == 0) ? x : x1;
        float* base = wt + (size_t)i * WT_L;

        ln_k<<<MT, blk>>>(xin, lng, lnb, xn);

        gemm_tc<EPI_NONE, false, false, true><<<gp, blk, SMEM_B>>>(xn, base + 0 * M4, q,
            Hdim, Hdim, Hdim, Hdim, 0, 0, 0, 0, 0, 0, 1, nullptr, nullptr);
        gemm_tc<EPI_NONE, false, false, true><<<gp, blk, SMEM_B>>>(xn, base + 1 * M4, k,
            Hdim, Hdim, Hdim, Hdim, 0, 0, 0, 0, 0, 0, 1, nullptr, nullptr);
        gemm_tc<EPI_NONE, false, true, true><<<gp, blk, SMEM_B>>>(xn, base + 2 * M4, vT,
            Hdim, Hdim, Hdim, Hdim, 0, 0, 0, 0, 0, 0, 1, nullptr, nullptr);
        gemm_tc<EPI_NONE, false, false, false><<<gp, blk, SMEM_B>>>(xn, base + 3 * M4, gt,
            Hdim, Hdim, Hdim, Hdim, 0, 0, 0, 0, 0, 0, 1, nullptr, nullptr);

        // scores = (q @ k^T) * D : A=q slice, B=k slice (both [*, K=HD], lda/ldb=Hdim)
        dim3 gs(Sn / BN, Sn / BM, Bn * NH);
        gemm_tc<EPI_DECAY, false, false, true><<<gs, blk, SMEM_B>>>(q, k, sc,
            HD, Hdim, Hdim, Sn,
            (long long)Sn * Hdim, (long long)HD,
            (long long)Sn * Hdim, (long long)HD,
            (long long)NH * Sn * Sn, (long long)Sn * Sn, NH, nullptr, nullptr);

        // y = scores @ v : A=sc [S,S], B=vT [HD, S], K clamped causal
        dim3 gy(HD / BN, Sn / BM, Bn * NH);
        gemm_tc<EPI_NONE, true, false, false><<<gy, blk, SMEM_B>>>(sc, vT, y,
            Sn, Sn, Sn, Hdim,
            (long long)NH * Sn * Sn, (long long)Sn * Sn,
            (long long)Hdim * Sn, (long long)HD * Sn,
            (long long)Sn * Hdim, (long long)HD, NH, nullptr, nullptr);

        gn_gate_k<<<MT * NH, blk>>>(y, gt, gng + (size_t)i * Hdim,
                                    gnb + (size_t)i * Hdim, zb);

        gemm_tc<EPI_RES, false, false, false><<<gp, blk, SMEM_B>>>(zb, base + 4 * M4, ret,
            Hdim, Hdim, Hdim, Hdim, 0, 0, 0, 0, 0, 0, 1, nullptr, xin);

        ln_k<<<MT, blk>>>(ret, lng, lnb, xn);

        dim3 g1(FFdim / BN, MT / BM, 1);
        gemm_tc<EPI_BIAS_GELU, false, false, true><<<g1, blk, SMEM_B>>>(xn, base + 5 * M4,
            ffn, Hdim, Hdim, Hdim, FFdim,
            0, 0, 0, 0, 0, 0, 1, b1 + (size_t)i * FFdim, nullptr);

        float* dst = (i == LAYERS - 1) ? out : x1;
        gemm_tc<EPI_BIAS_RES, false, false, false><<<gp, blk, SMEM_B>>>(ffn,
            base + 5 * M4 + M16, dst, FFdim, FFdim, FFdim, Hdim,
            0, 0, 0, 0, 0, 0, 1, b2 + (size_t)i * Hdim, ret);
    }
}